// round 6
// baseline (speedup 1.0000x reference)
#include <cuda_runtime.h>
#include <math.h>

// Radon forward projection, 512x512 img -> [512,512] sinogram (both axes flipped).
// R5: SHEARED quad tables. Warp lanes = 32 adjacent detectors on a line of
//     slope m (|m|<=1 after transpose). Tables stored with integer column row
//     shift floor(kn*c/2), kn = round(-2m) in {-2..2}, so the lanes' effective
//     row slope is <= 0.25 -> ~2-3x fewer L1 wavefronts per LDG.128.
//     10 tables (2 orientations x 5 shears), 69 MB, L2-resident.

#define IMG_N   512
#define N_ANG   512
#define N_DET   512
#define N_SAMP  256

#define PAD     3
#define TW      (IMG_N + 2*PAD + 2)     // 520

// Table row layout (row counts): per orientation kn=-2:1040, -1:780, 0:520,
// +1:780, +2:1040  => 4160 rows; two orientations => 8320 rows of 520 float4.
#define ROWS_PER_ORIENT 4160
#define TOT_ROWS        8320

__device__ float4 g_tabs[TOT_ROWS * TW];        // 69.2 MB

// row starts for (orient, kn): orient*5 + (kn+2)
__device__ __constant__ int c_rowstart[10] =
    {0, 1040, 1820, 2340, 3120,  4160, 5200, 5980, 6500, 7280};
// row offset so shifted rows stay >= 0 (index kn+2)
__device__ __constant__ int c_off[5] = {519, 260, 0, 0, 0};

// ---------------- stage 1: base quad tables (kn = 0) ----------------
__global__ __launch_bounds__(256) void build_base(const float* __restrict__ img)
{
    const int idx = blockIdx.x * 256 + threadIdx.x;
    if (idx >= TW * TW) return;
    const int py = idx / TW, px = idx % TW;
    const int r = py - PAD, c = px - PAD;

    const bool r0 = ((unsigned)r       < (unsigned)IMG_N);
    const bool r1 = ((unsigned)(r + 1) < (unsigned)IMG_N);
    const bool c0 = ((unsigned)c       < (unsigned)IMG_N);
    const bool c1 = ((unsigned)(c + 1) < (unsigned)IMG_N);

    float4 q;
    q.x = (r0 && c0) ? img[r * IMG_N + c]           : 0.0f;
    q.y = (r0 && c1) ? img[r * IMG_N + c + 1]       : 0.0f;
    q.z = (r1 && c0) ? img[(r + 1) * IMG_N + c]     : 0.0f;
    q.w = (r1 && c1) ? img[(r + 1) * IMG_N + c + 1] : 0.0f;
    g_tabs[(1820 + py) * TW + px] = q;              // orient 0, kn=0

    float4 t;                                       // transposed image
    t.x = (r0 && c0) ? img[c * IMG_N + r]           : 0.0f;
    t.y = (r0 && c1) ? img[(c + 1) * IMG_N + r]     : 0.0f;
    t.z = (r1 && c0) ? img[c * IMG_N + r + 1]       : 0.0f;
    t.w = (r1 && c1) ? img[(c + 1) * IMG_N + r + 1] : 0.0f;
    g_tabs[(5980 + py) * TW + px] = t;              // orient 1, kn=0
}

// ---------------- stage 2: shear expansion ----------------
__device__ __constant__ int c_sh_src [8] = {1820,1820,1820,1820, 5980,5980,5980,5980};
__device__ __constant__ int c_sh_dst [8] = {0, 1040, 2340, 3120,  4160, 5200, 6500, 7280};
__device__ __constant__ int c_sh_kn  [8] = {-2, -1, 1, 2,  -2, -1, 1, 2};
__device__ __constant__ int c_sh_off [8] = {519, 260, 0, 0,  519, 260, 0, 0};

__global__ __launch_bounds__(256) void build_shears()
{
    const int idx = blockIdx.x * 256 + threadIdx.x;
    if (idx >= TW * TW) return;
    const int t  = blockIdx.y;                      // 0..7
    const int r  = idx / TW, c = idx % TW;
    const int kn = c_sh_kn[t];
    const int rp = r + ((kn * c) >> 1) + c_sh_off[t];
    g_tabs[(c_sh_dst[t] + rp) * TW + c] = g_tabs[(c_sh_src[t] + r) * TW + c];
}

// ---------------- radon ----------------
__device__ __forceinline__ void clip_axis(float c0, float dc, float& lo, float& hi)
{
    const float L = 1.0f, H = (float)(TW - 3);      // [1, 517]
    if (fabsf(dc) > 1e-9f) {
        const float t0 = (L - c0) / dc;
        const float t1 = (H - c0) / dc;
        lo = fmaxf(lo, fminf(t0, t1));
        hi = fminf(hi, fmaxf(t0, t1));
    } else if (c0 <= L || c0 >= H) {
        lo = 1.0e9f; hi = -1.0e9f;
    }
}

__global__ __launch_bounds__(256) void radon_fwd_kernel(float* __restrict__ out)
{
    const int widx = threadIdx.x >> 5;
    const int lane = threadIdx.x & 31;
    const int wg   = blockIdx.x * 8 + widx;   // 0..16383

    const int h   = wg & 1;                   // s-half
    const int rid = wg >> 1;                  // 0..8191

    const int a     = (rid * 341) & 511;      // angle permutation (balance)
    const int chunk = rid >> 9;               // 0..15
    const int d     = chunk * 32 + lane;      // detector

    const float ang = fmaf((float)a, (float)(M_PI / 511.0), (float)(M_PI / 2.0));
    const float sa = sinf(ang);
    const float ca = cosf(ang);

    const float SQRT2 = 1.41421356237309515f;
    const float sx = fmaf((float)d, 2.0f / 511.0f, -1.0f);

    const float rsx = fmaf(sx, ca,  SQRT2 * sa);
    const float rsy = fmaf(sx, sa, -SQRT2 * ca);
    const float rdx = -2.0f * SQRT2 * sa;
    const float rdy =  2.0f * SQRT2 * ca;

    // shifted pixel coords (pad included) and per-s-step deltas
    float x0p = fmaf(rsx, 255.5f, 255.5f + (float)PAD);
    float y0p = fmaf(rsy, 255.5f, 255.5f + (float)PAD);
    float dxp = rdx * (255.5f / 256.0f);
    float dyp = rdy * (255.5f / 256.0f);

    // orientation: per-lane (detector) step is (ca, sa) px; keep |x-step| largest
    const int orient = (fabsf(sa) > fabsf(ca)) ? 1 : 0;
    float cxp = ca, cyp = sa;
    if (orient) {
        float t;
        t = x0p; x0p = y0p; y0p = t;
        t = dxp; dxp = dyp; dyp = t;
        cxp = sa; cyp = ca;
    }

    // shear selection: residual lane row-slope = cyp + (kn/2)*cxp, |.| <= 0.25
    int kn = __float2int_rn(-2.0f * cyp / cxp);
    kn = max(-2, min(2, kn));

    const int rowstart = c_rowstart[orient * 5 + (kn + 2)];
    const int off      = c_off[kn + 2];
    const float4* tp   = g_tabs + (rowstart + off) * TW;

    // clip sample range to table interior
    float lo = 0.0f, hi = (float)(N_SAMP - 1);
    clip_axis(x0p, dxp, lo, hi);
    clip_axis(y0p, dyp, lo, hi);
    int s0 = (lo > 0.0f) ? (int)ceilf(lo) : 0;
    int s1 = (hi < (float)(N_SAMP - 1)) ? (int)floorf(hi) : (N_SAMP - 1);

    const int hs0 = h * (N_SAMP / 2);
    const int hs1 = hs0 + (N_SAMP / 2) - 1;
    s0 = max(s0, hs0);
    s1 = min(s1, hs1);
    if (s0 > s1) return;

    float sum = 0.0f;

    #pragma unroll 4
    for (int s = s0; s <= s1; ++s) {
        const float x = fmaf((float)s, dxp, x0p);
        const float y = fmaf((float)s, dyp, y0p);

        const float xf = floorf(x);
        const float yf = floorf(y);
        const float fx = x - xf;
        const float fy = y - yf;

        const int c  = (int)xf;
        const int rp = (int)yf + ((kn * c) >> 1);   // sheared row

        const float4 q = __ldg(tp + rp * TW + c);

        const float top = fmaf(fx, q.y - q.x, q.x);
        const float bot = fmaf(fx, q.w - q.z, q.z);
        sum += fmaf(fy, bot - top, top);
    }

    const int o = (N_ANG - 1 - a) * N_DET + (N_DET - 1 - d);
    atomicAdd(out + o, sum * (1.0f / (float)N_SAMP));
}

extern "C" void kernel_launch(void* const* d_in, const int* in_sizes, int n_in,
                              void* d_out, int out_size)
{
    const float* img = (const float*)d_in[0];
    float* out = (float*)d_out;

    cudaMemsetAsync(out, 0, N_ANG * N_DET * sizeof(float));

    const int nb = (TW * TW + 255) / 256;
    build_base<<<nb, 256>>>(img);
    dim3 sg(nb, 8);
    build_shears<<<sg, 256>>>();

    // 512 angles * 16 det-warps * 2 s-halves = 16384 warps = 2048 blocks of 256
    radon_fwd_kernel<<<2048, 256>>>(out);
}

// round 7
// speedup vs baseline: 1.0481x; 1.0481x over previous
#include <cuda_runtime.h>
#include <math.h>

// Radon forward projection, 512x512 img -> [512,512] sinogram (both axes flipped).
// R6: single fused table-build kernel (smem-tiled, both orientations + all 5
//     shears written directly from registers), sheared quad tables as in R5,
//     radon kernel unchanged (1 LDG.128/sample, residual lane row-slope <=0.25).

#define IMG_N   512
#define N_ANG   512
#define N_DET   512
#define N_SAMP  256

#define PAD     3
#define TW      (IMG_N + 2*PAD + 2)     // 520

#define TOT_ROWS 8320                   // 2 orients x (1040+780+520+780+1040)

__device__ float4 g_tabs[TOT_ROWS * TW];

// row starts for (orient, kn): orient*5 + (kn+2)
__device__ __constant__ int c_rowstart[10] =
    {0, 1040, 1820, 2340, 3120,  4160, 5200, 5980, 6500, 7280};
__device__ __constant__ int c_off[5] = {519, 260, 0, 0, 0};

// ---------------- fused table build ----------------
// Block (bx,by): loads img patch rows [by*32-3, by*32+30], cols [bx*32-3, bx*32+30]
// (34x34) into smem. Emits orient-0 table tile (by,bx) and orient-1 table tile
// (bx,by), each to all 5 shear tables.
__global__ __launch_bounds__(256) void build_tables(const float* __restrict__ img)
{
    __shared__ float sm[34 * 35];

    const int tx = threadIdx.x;              // 0..31
    const int ty = threadIdx.y;              // 0..7
    const int tid = ty * 32 + tx;
    const int base_r = blockIdx.y * 32 - PAD;
    const int base_c = blockIdx.x * 32 - PAD;

    for (int idx = tid; idx < 34 * 34; idx += 256) {
        const int li = idx / 34, lj = idx % 34;
        const int r = base_r + li, c = base_c + lj;
        const bool v = ((unsigned)r < (unsigned)IMG_N) && ((unsigned)c < (unsigned)IMG_N);
        sm[li * 35 + lj] = v ? img[r * IMG_N + c] : 0.0f;
    }
    __syncthreads();

    #pragma unroll
    for (int k = 0; k < 4; ++k) {
        const int i = ty + 8 * k;            // local row 0..31

        // ---- orient 0: table tile (row=by, col=bx) ----
        const int py = blockIdx.y * 32 + i;
        const int px = blockIdx.x * 32 + tx;
        if (py < TW && px < TW) {
            float4 q;
            q.x = sm[i * 35 + tx];
            q.y = sm[i * 35 + tx + 1];
            q.z = sm[(i + 1) * 35 + tx];
            q.w = sm[(i + 1) * 35 + tx + 1];
            #pragma unroll
            for (int kn = -2; kn <= 2; ++kn) {
                const int row = c_rowstart[kn + 2] + c_off[kn + 2]
                              + py + ((kn * px) >> 1);
                g_tabs[row * TW + px] = q;
            }
        }

        // ---- orient 1 (transposed img): table tile (row=bx, col=by) ----
        const int py2 = blockIdx.x * 32 + i;
        const int px2 = blockIdx.y * 32 + tx;
        if (py2 < TW && px2 < TW) {
            float4 q;                        // zT(r,c)=z(c,r): transposed smem read
            q.x = sm[tx * 35 + i];
            q.y = sm[(tx + 1) * 35 + i];
            q.z = sm[tx * 35 + i + 1];
            q.w = sm[(tx + 1) * 35 + i + 1];
            #pragma unroll
            for (int kn = -2; kn <= 2; ++kn) {
                const int row = c_rowstart[5 + kn + 2] + c_off[kn + 2]
                              + py2 + ((kn * px2) >> 1);
                g_tabs[row * TW + px2] = q;
            }
        }
    }
}

// ---------------- radon ----------------
__device__ __forceinline__ void clip_axis(float c0, float dc, float& lo, float& hi)
{
    const float L = 1.0f, H = (float)(TW - 3);      // [1, 517]
    if (fabsf(dc) > 1e-9f) {
        const float t0 = (L - c0) / dc;
        const float t1 = (H - c0) / dc;
        lo = fmaxf(lo, fminf(t0, t1));
        hi = fminf(hi, fmaxf(t0, t1));
    } else if (c0 <= L || c0 >= H) {
        lo = 1.0e9f; hi = -1.0e9f;
    }
}

__global__ __launch_bounds__(256) void radon_fwd_kernel(float* __restrict__ out)
{
    const int widx = threadIdx.x >> 5;
    const int lane = threadIdx.x & 31;
    const int wg   = blockIdx.x * 8 + widx;   // 0..16383

    const int h   = wg & 1;                   // s-half
    const int rid = wg >> 1;                  // 0..8191

    const int a     = (rid * 341) & 511;      // angle permutation (balance)
    const int chunk = rid >> 9;               // 0..15
    const int d     = chunk * 32 + lane;      // detector

    const float ang = fmaf((float)a, (float)(M_PI / 511.0), (float)(M_PI / 2.0));
    const float sa = sinf(ang);
    const float ca = cosf(ang);

    const float SQRT2 = 1.41421356237309515f;
    const float sx = fmaf((float)d, 2.0f / 511.0f, -1.0f);

    const float rsx = fmaf(sx, ca,  SQRT2 * sa);
    const float rsy = fmaf(sx, sa, -SQRT2 * ca);
    const float rdx = -2.0f * SQRT2 * sa;
    const float rdy =  2.0f * SQRT2 * ca;

    float x0p = fmaf(rsx, 255.5f, 255.5f + (float)PAD);
    float y0p = fmaf(rsy, 255.5f, 255.5f + (float)PAD);
    float dxp = rdx * (255.5f / 256.0f);
    float dyp = rdy * (255.5f / 256.0f);

    // orientation: keep |x-step| of the lane (detector) direction largest
    const int orient = (fabsf(sa) > fabsf(ca)) ? 1 : 0;
    float cxp = ca, cyp = sa;
    if (orient) {
        float t;
        t = x0p; x0p = y0p; y0p = t;
        t = dxp; dxp = dyp; dyp = t;
        cxp = sa; cyp = ca;
    }

    // shear: residual lane row-slope = cyp + (kn/2)*cxp, |.| <= 0.25
    int kn = __float2int_rn(-2.0f * cyp / cxp);
    kn = max(-2, min(2, kn));

    const int rowstart = c_rowstart[orient * 5 + (kn + 2)];
    const int off      = c_off[kn + 2];
    const float4* tp   = g_tabs + (rowstart + off) * TW;

    float lo = 0.0f, hi = (float)(N_SAMP - 1);
    clip_axis(x0p, dxp, lo, hi);
    clip_axis(y0p, dyp, lo, hi);
    int s0 = (lo > 0.0f) ? (int)ceilf(lo) : 0;
    int s1 = (hi < (float)(N_SAMP - 1)) ? (int)floorf(hi) : (N_SAMP - 1);

    const int hs0 = h * (N_SAMP / 2);
    const int hs1 = hs0 + (N_SAMP / 2) - 1;
    s0 = max(s0, hs0);
    s1 = min(s1, hs1);
    if (s0 > s1) return;

    float sum = 0.0f;

    #pragma unroll 4
    for (int s = s0; s <= s1; ++s) {
        const float x = fmaf((float)s, dxp, x0p);
        const float y = fmaf((float)s, dyp, y0p);

        const float xf = floorf(x);
        const float yf = floorf(y);
        const float fx = x - xf;
        const float fy = y - yf;

        const int c  = (int)xf;
        const int rp = (int)yf + ((kn * c) >> 1);   // sheared row

        const float4 q = __ldg(tp + rp * TW + c);

        const float top = fmaf(fx, q.y - q.x, q.x);
        const float bot = fmaf(fx, q.w - q.z, q.z);
        sum += fmaf(fy, bot - top, top);
    }

    const int o = (N_ANG - 1 - a) * N_DET + (N_DET - 1 - d);
    atomicAdd(out + o, sum * (1.0f / (float)N_SAMP));
}

extern "C" void kernel_launch(void* const* d_in, const int* in_sizes, int n_in,
                              void* d_out, int out_size)
{
    const float* img = (const float*)d_in[0];
    float* out = (float*)d_out;

    cudaMemsetAsync(out, 0, N_ANG * N_DET * sizeof(float));

    dim3 bt(32, 8);
    dim3 bg((TW + 31) / 32, (TW + 31) / 32);   // 17 x 17 tiles
    build_tables<<<bg, bt>>>(img);

    // 512 angles * 16 det-warps * 2 s-halves = 16384 warps = 2048 blocks of 256
    radon_fwd_kernel<<<2048, 256>>>(out);
}

// round 10
// speedup vs baseline: 1.1927x; 1.1379x over previous
#include <cuda_runtime.h>
#include <cuda_fp16.h>
#include <math.h>

// Radon forward projection, 512x512 img -> [512,512] sinogram (both axes flipped).
// R8 (= R7 with compile fix): fp16x2 QUAD tables — each 2x2 bilinear footprint
//     packed in 8 bytes, so the inner loop is ONE LDG.64 per sample (warp
//     footprint 256B). Sheared layouts (5 per orientation) bound lane
//     row-slope <=0.25. Interpolation in fp32. Tables: 35 MB, L2-resident.

#define IMG_N   512
#define N_ANG   512
#define N_DET   512
#define N_SAMP  256

#define PAD     3
#define TW      (IMG_N + 2*PAD + 2)     // 520

#define TOT_ROWS 8320                   // 2 orients x (1040+780+520+780+1040)

// entry: .x = half2(q00,q01) (top row), .y = half2(q10,q11) (bottom row)
__device__ uint2 g_tabs[TOT_ROWS * TW];     // 34.6 MB

// row starts for (orient, kn): orient*5 + (kn+2)
__device__ __constant__ int c_rowstart[10] =
    {0, 1040, 1820, 2340, 3120,  4160, 5200, 5980, 6500, 7280};
__device__ __constant__ int c_off[5] = {519, 260, 0, 0, 0};

__device__ __forceinline__ unsigned h2_bits(__half2 h)
{
    return *reinterpret_cast<unsigned*>(&h);
}
__device__ __forceinline__ __half2 bits_h2(unsigned u)
{
    return *reinterpret_cast<__half2*>(&u);
}

// ---------------- fused table build ----------------
__global__ __launch_bounds__(256) void build_tables(const float* __restrict__ img)
{
    __shared__ float sm[34 * 35];

    const int tx = threadIdx.x;              // 0..31
    const int ty = threadIdx.y;              // 0..7
    const int tid = ty * 32 + tx;
    const int base_r = blockIdx.y * 32 - PAD;
    const int base_c = blockIdx.x * 32 - PAD;

    for (int idx = tid; idx < 34 * 34; idx += 256) {
        const int li = idx / 34, lj = idx % 34;
        const int r = base_r + li, c = base_c + lj;
        const bool v = ((unsigned)r < (unsigned)IMG_N) && ((unsigned)c < (unsigned)IMG_N);
        sm[li * 35 + lj] = v ? img[r * IMG_N + c] : 0.0f;
    }
    __syncthreads();

    #pragma unroll
    for (int k = 0; k < 4; ++k) {
        const int i = ty + 8 * k;            // local row 0..31

        // ---- orient 0: table tile (row=by, col=bx) ----
        const int py = blockIdx.y * 32 + i;
        const int px = blockIdx.x * 32 + tx;
        if (py < TW && px < TW) {
            uint2 q;
            q.x = h2_bits(__floats2half2_rn(sm[i * 35 + tx],       sm[i * 35 + tx + 1]));
            q.y = h2_bits(__floats2half2_rn(sm[(i + 1) * 35 + tx], sm[(i + 1) * 35 + tx + 1]));
            #pragma unroll
            for (int kn = -2; kn <= 2; ++kn) {
                const int row = c_rowstart[kn + 2] + c_off[kn + 2]
                              + py + ((kn * px) >> 1);
                g_tabs[row * TW + px] = q;
            }
        }

        // ---- orient 1 (transposed img): table tile (row=bx, col=by) ----
        const int py2 = blockIdx.x * 32 + i;
        const int px2 = blockIdx.y * 32 + tx;
        if (py2 < TW && px2 < TW) {
            uint2 q;                         // zT(r,c)=z(c,r): transposed smem read
            q.x = h2_bits(__floats2half2_rn(sm[tx * 35 + i],     sm[(tx + 1) * 35 + i]));
            q.y = h2_bits(__floats2half2_rn(sm[tx * 35 + i + 1], sm[(tx + 1) * 35 + i + 1]));
            #pragma unroll
            for (int kn = -2; kn <= 2; ++kn) {
                const int row = c_rowstart[5 + kn + 2] + c_off[kn + 2]
                              + py2 + ((kn * px2) >> 1);
                g_tabs[row * TW + px2] = q;
            }
        }
    }
}

// ---------------- radon ----------------
__device__ __forceinline__ void clip_axis(float c0, float dc, float& lo, float& hi)
{
    const float L = 1.0f, H = (float)(TW - 3);      // [1, 517]
    if (fabsf(dc) > 1e-9f) {
        const float t0 = (L - c0) / dc;
        const float t1 = (H - c0) / dc;
        lo = fmaxf(lo, fminf(t0, t1));
        hi = fminf(hi, fmaxf(t0, t1));
    } else if (c0 <= L || c0 >= H) {
        lo = 1.0e9f; hi = -1.0e9f;
    }
}

__global__ __launch_bounds__(256) void radon_fwd_kernel(float* __restrict__ out)
{
    const int widx = threadIdx.x >> 5;
    const int lane = threadIdx.x & 31;
    const int wg   = blockIdx.x * 8 + widx;   // 0..16383

    const int h   = wg & 1;                   // s-half
    const int rid = wg >> 1;                  // 0..8191

    const int a     = (rid * 341) & 511;      // angle permutation (balance)
    const int chunk = rid >> 9;               // 0..15
    const int d     = chunk * 32 + lane;      // detector

    const float ang = fmaf((float)a, (float)(M_PI / 511.0), (float)(M_PI / 2.0));
    const float sa = sinf(ang);
    const float ca = cosf(ang);

    const float SQRT2 = 1.41421356237309515f;
    const float sx = fmaf((float)d, 2.0f / 511.0f, -1.0f);

    const float rsx = fmaf(sx, ca,  SQRT2 * sa);
    const float rsy = fmaf(sx, sa, -SQRT2 * ca);
    const float rdx = -2.0f * SQRT2 * sa;
    const float rdy =  2.0f * SQRT2 * ca;

    float x0p = fmaf(rsx, 255.5f, 255.5f + (float)PAD);
    float y0p = fmaf(rsy, 255.5f, 255.5f + (float)PAD);
    float dxp = rdx * (255.5f / 256.0f);
    float dyp = rdy * (255.5f / 256.0f);

    // orientation: keep |x-step| of the lane (detector) direction largest
    const int orient = (fabsf(sa) > fabsf(ca)) ? 1 : 0;
    float cxp = ca, cyp = sa;
    if (orient) {
        float t;
        t = x0p; x0p = y0p; y0p = t;
        t = dxp; dxp = dyp; dyp = t;
        cxp = sa; cyp = ca;
    }

    // shear: residual lane row-slope = cyp + (kn/2)*cxp, |.| <= 0.25
    int kn = __float2int_rn(-2.0f * cyp / cxp);
    kn = max(-2, min(2, kn));

    const int rowstart = c_rowstart[orient * 5 + (kn + 2)];
    const int off      = c_off[kn + 2];
    const uint2* tp    = g_tabs + (rowstart + off) * TW;

    float lo = 0.0f, hi = (float)(N_SAMP - 1);
    clip_axis(x0p, dxp, lo, hi);
    clip_axis(y0p, dyp, lo, hi);
    int s0 = (lo > 0.0f) ? (int)ceilf(lo) : 0;
    int s1 = (hi < (float)(N_SAMP - 1)) ? (int)floorf(hi) : (N_SAMP - 1);

    const int hs0 = h * (N_SAMP / 2);
    const int hs1 = hs0 + (N_SAMP / 2) - 1;
    s0 = max(s0, hs0);
    s1 = min(s1, hs1);
    if (s0 > s1) return;

    float sum = 0.0f;

    #pragma unroll 4
    for (int s = s0; s <= s1; ++s) {
        const float x = fmaf((float)s, dxp, x0p);
        const float y = fmaf((float)s, dyp, y0p);

        const float xf = floorf(x);
        const float yf = floorf(y);
        const float fx = x - xf;
        const float fy = y - yf;

        const int c  = (int)xf;
        const int rp = (int)yf + ((kn * c) >> 1);   // sheared row

        const uint2 qh = __ldg(tp + rp * TW + c);
        const float2 t = __half22float2(bits_h2(qh.x));  // q00,q01
        const float2 b = __half22float2(bits_h2(qh.y));  // q10,q11

        const float top = fmaf(fx, t.y - t.x, t.x);
        const float bot = fmaf(fx, b.y - b.x, b.x);
        sum += fmaf(fy, bot - top, top);
    }

    const int o = (N_ANG - 1 - a) * N_DET + (N_DET - 1 - d);
    atomicAdd(out + o, sum * (1.0f / (float)N_SAMP));
}

extern "C" void kernel_launch(void* const* d_in, const int* in_sizes, int n_in,
                              void* d_out, int out_size)
{
    const float* img = (const float*)d_in[0];
    float* out = (float*)d_out;

    cudaMemsetAsync(out, 0, N_ANG * N_DET * sizeof(float));

    dim3 bt(32, 8);
    dim3 bg((TW + 31) / 32, (TW + 31) / 32);   // 17 x 17 tiles
    build_tables<<<bg, bt>>>(img);

    // 512 angles * 16 det-warps * 2 s-halves = 16384 warps = 2048 blocks of 256
    radon_fwd_kernel<<<2048, 256>>>(out);
}

// round 11
// speedup vs baseline: 1.2664x; 1.0618x over previous
#include <cuda_runtime.h>
#include <cuda_fp16.h>
#include <math.h>

// Radon forward projection, 512x512 img -> [512,512] sinogram (both axes flipped).
// R10: instruction-diet on the issue-bound inner loop:
//      - blocked coordinate generation (FFMA-imm per sample, exact, no I2F)
//      - kn-specialized address math (even kn: 2 IMAD via uniform multiplier)
//      Memory layout unchanged from R9: fp16x2 quad tables, 5 shears x 2
//      orients (35 MB, L2-resident), one LDG.64 per bilinear sample.

#define IMG_N   512
#define N_ANG   512
#define N_DET   512
#define N_SAMP  256

#define PAD     3
#define TW      (IMG_N + 2*PAD + 2)     // 520

#define TOT_ROWS 8320                   // 2 orients x (1040+780+520+780+1040)

// entry: .x = half2(q00,q01) (top row), .y = half2(q10,q11) (bottom row)
__device__ uint2 g_tabs[TOT_ROWS * TW];     // 34.6 MB

// row starts for (orient, kn): orient*5 + (kn+2)
__device__ __constant__ int c_rowstart[10] =
    {0, 1040, 1820, 2340, 3120,  4160, 5200, 5980, 6500, 7280};
__device__ __constant__ int c_off[5] = {519, 260, 0, 0, 0};

__device__ __forceinline__ unsigned h2_bits(__half2 h)
{
    return *reinterpret_cast<unsigned*>(&h);
}
__device__ __forceinline__ __half2 bits_h2(unsigned u)
{
    return *reinterpret_cast<__half2*>(&u);
}

// ---------------- fused table build ----------------
__global__ __launch_bounds__(256) void build_tables(const float* __restrict__ img)
{
    __shared__ float sm[34 * 35];

    const int tx = threadIdx.x;              // 0..31
    const int ty = threadIdx.y;              // 0..7
    const int tid = ty * 32 + tx;
    const int base_r = blockIdx.y * 32 - PAD;
    const int base_c = blockIdx.x * 32 - PAD;

    for (int idx = tid; idx < 34 * 34; idx += 256) {
        const int li = idx / 34, lj = idx % 34;
        const int r = base_r + li, c = base_c + lj;
        const bool v = ((unsigned)r < (unsigned)IMG_N) && ((unsigned)c < (unsigned)IMG_N);
        sm[li * 35 + lj] = v ? img[r * IMG_N + c] : 0.0f;
    }
    __syncthreads();

    #pragma unroll
    for (int k = 0; k < 4; ++k) {
        const int i = ty + 8 * k;            // local row 0..31

        // ---- orient 0: table tile (row=by, col=bx) ----
        const int py = blockIdx.y * 32 + i;
        const int px = blockIdx.x * 32 + tx;
        if (py < TW && px < TW) {
            uint2 q;
            q.x = h2_bits(__floats2half2_rn(sm[i * 35 + tx],       sm[i * 35 + tx + 1]));
            q.y = h2_bits(__floats2half2_rn(sm[(i + 1) * 35 + tx], sm[(i + 1) * 35 + tx + 1]));
            #pragma unroll
            for (int kn = -2; kn <= 2; ++kn) {
                const int row = c_rowstart[kn + 2] + c_off[kn + 2]
                              + py + ((kn * px) >> 1);
                g_tabs[row * TW + px] = q;
            }
        }

        // ---- orient 1 (transposed img): table tile (row=bx, col=by) ----
        const int py2 = blockIdx.x * 32 + i;
        const int px2 = blockIdx.y * 32 + tx;
        if (py2 < TW && px2 < TW) {
            uint2 q;                         // zT(r,c)=z(c,r): transposed smem read
            q.x = h2_bits(__floats2half2_rn(sm[tx * 35 + i],     sm[(tx + 1) * 35 + i]));
            q.y = h2_bits(__floats2half2_rn(sm[tx * 35 + i + 1], sm[(tx + 1) * 35 + i + 1]));
            #pragma unroll
            for (int kn = -2; kn <= 2; ++kn) {
                const int row = c_rowstart[5 + kn + 2] + c_off[kn + 2]
                              + py2 + ((kn * px2) >> 1);
                g_tabs[row * TW + px2] = q;
            }
        }
    }
}

// ---------------- radon ----------------
__device__ __forceinline__ void clip_axis(float c0, float dc, float& lo, float& hi)
{
    const float L = 1.0f, H = (float)(TW - 3);      // [1, 517]
    if (fabsf(dc) > 1e-9f) {
        const float t0 = (L - c0) / dc;
        const float t1 = (H - c0) / dc;
        lo = fmaxf(lo, fminf(t0, t1));
        hi = fminf(hi, fmaxf(t0, t1));
    } else if (c0 <= L || c0 >= H) {
        lo = 1.0e9f; hi = -1.0e9f;
    }
}

// one bilinear sample at (x, y); idx address math specialized on shear parity
template<bool ODD>
__device__ __forceinline__ void sample_one(
    const uint2* __restrict__ tp, float x, float y, int M, int kn, float& sum)
{
    const float xf = floorf(x);
    const float yf = floorf(y);
    const float fx = x - xf;
    const float fy = y - yf;
    const int ix = (int)xf;
    const int iy = (int)yf;

    int idx;
    if (ODD) idx = (iy + ((kn * ix) >> 1)) * TW + ix;
    else     idx = iy * TW + ix * M;

    const uint2 qh = __ldg(tp + idx);
    const float2 t = __half22float2(bits_h2(qh.x));  // q00,q01
    const float2 b = __half22float2(bits_h2(qh.y));  // q10,q11

    const float top = fmaf(fx, t.y - t.x, t.x);
    const float bot = fmaf(fx, b.y - b.x, b.x);
    sum += fmaf(fy, bot - top, top);
}

template<bool ODD>
__device__ __forceinline__ float integrate(
    const uint2* __restrict__ tp,
    float x0p, float y0p, float dxp, float dyp,
    int s0, int s1, int M, int kn)
{
    float sum = 0.0f;
    const int n = s1 - s0 + 1;
    float sbf = (float)s0;                    // exact (s0 < 2^24)
    int i = 0;

    for (; i + 8 <= n; i += 8) {
        const float xb = fmaf(sbf, dxp, x0p); // exact integer base -> no drift
        const float yb = fmaf(sbf, dyp, y0p);
        sbf += 8.0f;
        #pragma unroll
        for (int j = 0; j < 8; ++j) {
            const float x = fmaf((float)j, dxp, xb);   // FFMA-imm (literal j)
            const float y = fmaf((float)j, dyp, yb);
            sample_one<ODD>(tp, x, y, M, kn, sum);
        }
    }
    if (i < n) {
        const float xb = fmaf(sbf, dxp, x0p);
        const float yb = fmaf(sbf, dyp, y0p);
        for (int j = 0; i + j < n; ++j) {
            const float x = fmaf((float)j, dxp, xb);
            const float y = fmaf((float)j, dyp, yb);
            sample_one<ODD>(tp, x, y, M, kn, sum);
        }
    }
    return sum;
}

__global__ __launch_bounds__(256, 6) void radon_fwd_kernel(float* __restrict__ out)
{
    const int widx = threadIdx.x >> 5;
    const int lane = threadIdx.x & 31;
    const int wg   = blockIdx.x * 8 + widx;   // 0..16383

    const int h   = wg & 1;                   // s-half
    const int rid = wg >> 1;                  // 0..8191

    const int a     = (rid * 341) & 511;      // angle permutation (balance)
    const int chunk = rid >> 9;               // 0..15
    const int d     = chunk * 32 + lane;      // detector

    const float ang = fmaf((float)a, (float)(M_PI / 511.0), (float)(M_PI / 2.0));
    const float sa = sinf(ang);
    const float ca = cosf(ang);

    const float SQRT2 = 1.41421356237309515f;
    const float sx = fmaf((float)d, 2.0f / 511.0f, -1.0f);

    const float rsx = fmaf(sx, ca,  SQRT2 * sa);
    const float rsy = fmaf(sx, sa, -SQRT2 * ca);
    const float rdx = -2.0f * SQRT2 * sa;
    const float rdy =  2.0f * SQRT2 * ca;

    float x0p = fmaf(rsx, 255.5f, 255.5f + (float)PAD);
    float y0p = fmaf(rsy, 255.5f, 255.5f + (float)PAD);
    float dxp = rdx * (255.5f / 256.0f);
    float dyp = rdy * (255.5f / 256.0f);

    // orientation: keep |x-step| of the lane (detector) direction largest
    const int orient = (fabsf(sa) > fabsf(ca)) ? 1 : 0;
    float cxp = ca, cyp = sa;
    if (orient) {
        float t;
        t = x0p; x0p = y0p; y0p = t;
        t = dxp; dxp = dyp; dyp = t;
        cxp = sa; cyp = ca;
    }

    // shear: residual lane row-slope = cyp + (kn/2)*cxp, |.| <= 0.25
    int kn = __float2int_rn(-2.0f * cyp / cxp);
    kn = max(-2, min(2, kn));

    const int rowstart = c_rowstart[orient * 5 + (kn + 2)];
    const int off      = c_off[kn + 2];
    const uint2* tp    = g_tabs + (rowstart + off) * TW;

    float lo = 0.0f, hi = (float)(N_SAMP - 1);
    clip_axis(x0p, dxp, lo, hi);
    clip_axis(y0p, dyp, lo, hi);
    int s0 = (lo > 0.0f) ? (int)ceilf(lo) : 0;
    int s1 = (hi < (float)(N_SAMP - 1)) ? (int)floorf(hi) : (N_SAMP - 1);

    const int hs0 = h * (N_SAMP / 2);
    const int hs1 = hs0 + (N_SAMP / 2) - 1;
    s0 = max(s0, hs0);
    s1 = min(s1, hs1);
    if (s0 > s1) return;

    const int M = 1 + (kn >> 1) * TW;         // even-kn column multiplier

    float sum;
    if (kn & 1) sum = integrate<true >(tp, x0p, y0p, dxp, dyp, s0, s1, M, kn);
    else        sum = integrate<false>(tp, x0p, y0p, dxp, dyp, s0, s1, M, kn);

    const int o = (N_ANG - 1 - a) * N_DET + (N_DET - 1 - d);
    atomicAdd(out + o, sum * (1.0f / (float)N_SAMP));
}

extern "C" void kernel_launch(void* const* d_in, const int* in_sizes, int n_in,
                              void* d_out, int out_size)
{
    const float* img = (const float*)d_in[0];
    float* out = (float*)d_out;

    cudaMemsetAsync(out, 0, N_ANG * N_DET * sizeof(float));

    dim3 bt(32, 8);
    dim3 bg((TW + 31) / 32, (TW + 31) / 32);   // 17 x 17 tiles
    build_tables<<<bg, bt>>>(img);

    // 512 angles * 16 det-warps * 2 s-halves = 16384 warps = 2048 blocks of 256
    radon_fwd_kernel<<<2048, 256>>>(out);
}